// round 10
// baseline (speedup 1.0000x reference)
#include <cuda_runtime.h>
#include <math.h>

// Problem constants
#define B_ 16
#define L_ 512
#define D_ 768
#define H_ 12
#define K_ 128
#define U_ 256
#define NH_ 4
#define HD_ 64

// Scratch (no init needed: fully overwritten every replay)
static __device__ __align__(16) float g_imp_part[B_*48*L_];     // (b, chunk48, l)
static __device__ __align__(16) float g_sent_part[B_*16*D_];    // (b, chunk16, d)
static __device__ __align__(16) float g_q[B_*U_];
static __device__ __align__(16) float g_t[B_*NH_*D_];
static __device__ __align__(16) float g_scores[B_*NH_*L_];
static __device__ __align__(16) float g_w_part[B_*16*NH_*D_];   // (b, chunk16, h, d)
static __device__ __align__(16) float g_o[B_*U_];
static __device__ __align__(16) float g_newtok[B_*D_];
static __device__ float g_warm[1024];
static __device__ int   g_idx[B_*K_];

__device__ __forceinline__ float warp_max(float v){
  #pragma unroll
  for (int o=16;o;o>>=1) v = fmaxf(v, __shfl_xor_sync(0xffffffffu, v, o));
  return v;
}
__device__ __forceinline__ float warp_sum(float v){
  #pragma unroll
  for (int o=16;o;o>>=1) v += __shfl_xor_sync(0xffffffffu, v, o);
  return v;
}
__device__ __forceinline__ float block_max(float v, float* red, int wid, int lane, int nw){
  v = warp_max(v);
  if (lane==0) red[wid] = v;
  __syncthreads();
  if (wid==0){
    float x = (lane < nw) ? red[lane] : -INFINITY;
    x = warp_max(x);
    if (lane==0) red[0] = x;
  }
  __syncthreads();
  float r = red[0];
  __syncthreads();
  return r;
}
__device__ __forceinline__ float block_sum(float v, float* red, int wid, int lane, int nw){
  v = warp_sum(v);
  if (lane==0) red[wid] = v;
  __syncthreads();
  if (wid==0){
    float x = (lane < nw) ? red[lane] : 0.f;
    x = warp_sum(x);
    if (lane==0) red[0] = x;
  }
  __syncthreads();
  float r = red[0];
  __syncthreads();
  return r;
}
__device__ __forceinline__ float dot4(float4 a, float4 b){
  return a.x*b.x + a.y*b.y + a.z*b.z + a.w*b.w;
}

// ---------------------------------------------------------------------------
// Warm L2 with the weight matrices (deterministic, result unused downstream).
// grid 768, 256 threads: 4 matrices x 49152 float4 = 3 MB.
__global__ void __launch_bounds__(256) k_warm(const float4* __restrict__ Wq,
                                              const float4* __restrict__ Wk,
                                              const float4* __restrict__ Wv,
                                              const float4* __restrict__ Wo){
  int i = blockIdx.x*256 + threadIdx.x;   // 0 .. 196607
  int m = i / 49152;
  const float4* src = (m==0) ? Wq : (m==1) ? Wk : (m==2) ? Wv : Wo;
  int off = i - m*49152;
  float4 v = src[off];
  float s = v.x + v.y + v.z + v.w;
  s = warp_sum(s);
  if (threadIdx.x == 0)
    g_warm[blockIdx.x] = s;
}

// ---------------------------------------------------------------------------
// importance partials: g_imp_part[b,ch,l] = (1/H)*sum_{128 rows} sas[b,rows,l]
// grid (B, 48), 256 threads. __ldcs: 201 MB read exactly once — evict-first
// keeps hidden_states L2-resident for the attention chain.
__global__ void __launch_bounds__(256) k_importance(const float* __restrict__ s){
  __shared__ float4 s_half[128];
  int b = blockIdx.x, ch = blockIdx.y;
  int col = threadIdx.x & 127;
  int rh  = threadIdx.x >> 7;
  const float4* base = (const float4*)s + (size_t)(b*H_*L_ + ch*128) * (L_/4);
  float4 acc = make_float4(0.f,0.f,0.f,0.f);
  #pragma unroll 16
  for (int r = rh; r < 128; r += 2){
    float4 v = __ldcs(&base[(size_t)r*(L_/4) + col]);
    acc.x += v.x; acc.y += v.y; acc.z += v.z; acc.w += v.w;
  }
  if (rh == 1) s_half[col] = acc;
  __syncthreads();
  if (rh == 0){
    const float sc = 1.0f/(float)H_;
    float4 o = s_half[col];
    o.x = (o.x + acc.x)*sc; o.y = (o.y + acc.y)*sc;
    o.z = (o.z + acc.z)*sc; o.w = (o.w + acc.w)*sc;
    __stcs(&((float4*)(g_imp_part + (size_t)(b*48 + ch)*L_))[col], o);
  }
}

// ---------------------------------------------------------------------------
// top-K: reduce 48 partials, rank with jax tie rule, compact by index.
__global__ void __launch_bounds__(512) k_topk(){
  __shared__ float v[L_];
  __shared__ int flag[L_];
  int b = blockIdx.x, tid = threadIdx.x;
  float acc = 0.f;
  #pragma unroll
  for (int c = 0; c < 48; c++)
    acc += g_imp_part[(size_t)(b*48 + c)*L_ + tid];
  v[tid] = acc;
  __syncthreads();
  float mv = v[tid];
  int r = 0;
  #pragma unroll 8
  for (int j = 0; j < L_; j++){
    float o = v[j];
    r += (o > mv) || (o == mv && j < tid);
  }
  int sel = (r < K_) ? 1 : 0;
  flag[tid] = sel;
  __syncthreads();
  if (sel){
    int pos = 0;
    for (int j = 0; j < tid; j++) pos += flag[j];
    g_idx[b*K_ + pos] = tid;
  }
}

// ---------------------------------------------------------------------------
// Fused mask-softmax + sentence partials.  grid (B, 16), 768 threads;
// each block handles 32 l's -> g_sent_part[b,ch,:]
__global__ void __launch_bounds__(768) k_sent(const float* __restrict__ hs,
                                              const float* __restrict__ mask){
  __shared__ float s_att[L_];
  __shared__ float red[32];
  int b = blockIdx.x, ch = blockIdx.y;
  int tid = threadIdx.x, wid = tid>>5, lane = tid&31;
  float mv = (tid < L_) ? mask[b*L_ + tid] : -INFINITY;
  float m = block_max(mv, red, wid, lane, 24);
  float e = (tid < L_) ? expf(mv - m) : 0.f;
  float ssum = block_sum(e, red, wid, lane, 24);
  if (tid < L_) s_att[tid] = e / ssum;
  __syncthreads();
  float acc = 0.f;
  int l0 = ch*32;
  const float* hb = hs + ((size_t)b*L_ + l0)*D_ + tid;
  #pragma unroll 8
  for (int l = 0; l < 32; l++)
    acc += s_att[l0+l] * hb[(size_t)l*D_];
  g_sent_part[(size_t)(b*16 + ch)*D_ + tid] = acc;
}

// ---------------------------------------------------------------------------
// q[b,u] = sent[b]·Wq[u,:]  (reduce 16 sent partials in-block)
// grid (B, 32), 256 threads; warp per u
__global__ void __launch_bounds__(256) k_q(const float* __restrict__ Wq){
  __shared__ __align__(16) float s_sent[D_];
  int b = blockIdx.x, ch = blockIdx.y;
  int tid = threadIdx.x, wid = tid>>5, lane = tid&31;
  if (tid < 192){
    float4 a = make_float4(0.f,0.f,0.f,0.f);
    #pragma unroll
    for (int c = 0; c < 16; c++){
      float4 v = ((const float4*)(g_sent_part + (size_t)(b*16 + c)*D_))[tid];
      a.x += v.x; a.y += v.y; a.z += v.z; a.w += v.w;
    }
    ((float4*)s_sent)[tid] = a;
  }
  __syncthreads();
  const float4* s4 = (const float4*)s_sent;
  int u = ch*8 + wid;
  const float4* wr = (const float4*)(Wq + (size_t)u*D_);
  float acc = 0.f;
  #pragma unroll
  for (int k = 0; k < 6; k++) acc += dot4(s4[lane + 32*k], wr[lane + 32*k]);
  acc = warp_sum(acc);
  if (lane==0) g_q[b*U_ + u] = acc;
}

// ---------------------------------------------------------------------------
// t[b,h,d] = sum_j q[b,h*64+j]*Wk[h*64+j,d]   grid (B, NH, 6), 128 threads
__global__ void __launch_bounds__(128) k_t(const float* __restrict__ Wk){
  __shared__ float s_q[HD_];
  int b = blockIdx.x, h = blockIdx.y, z = blockIdx.z;
  int tid = threadIdx.x;
  if (tid < HD_) s_q[tid] = g_q[b*U_ + h*HD_ + tid];
  __syncthreads();
  int d = z*128 + tid;
  const float* wk = Wk + (size_t)h*HD_*D_ + d;
  float acc = 0.f;
  #pragma unroll 16
  for (int j = 0; j < HD_; j++)
    acc += s_q[j] * wk[(size_t)j*D_];
  g_t[(b*NH_+h)*D_ + d] = acc;
}

// ---------------------------------------------------------------------------
// scores[b,h,l] = (t[b,h]·hidden[b,l]) / sqrt(D), masked -> -inf
// grid (B, 32), 512 threads (16 warps); warp per l
__global__ void __launch_bounds__(512) k_scores(const float* __restrict__ hs,
                                                const float* __restrict__ mask){
  __shared__ __align__(16) float s_t[NH_*D_];
  int b = blockIdx.x, ch = blockIdx.y;
  int tid = threadIdx.x, wid = tid>>5, lane = tid&31;
  for (int i = tid; i < NH_*192; i += 512)
    ((float4*)s_t)[i] = ((const float4*)(g_t + b*NH_*D_))[i];
  __syncthreads();
  const float4* t4 = (const float4*)s_t;
  const float inv_sqrt_d = 0.03608439182435161f; // 1/sqrt(768)
  int l = ch*16 + wid;
  const float4* hr = (const float4*)(hs + ((size_t)b*L_ + l)*D_);
  float a0=0.f,a1=0.f,a2=0.f,a3=0.f;
  #pragma unroll
  for (int k = 0; k < 6; k++){
    float4 v  = hr[lane + 32*k];
    a0 += dot4(v, t4[0*192 + lane + 32*k]);
    a1 += dot4(v, t4[1*192 + lane + 32*k]);
    a2 += dot4(v, t4[2*192 + lane + 32*k]);
    a3 += dot4(v, t4[3*192 + lane + 32*k]);
  }
  a0 = warp_sum(a0); a1 = warp_sum(a1); a2 = warp_sum(a2); a3 = warp_sum(a3);
  if (lane == 0){
    bool pad = mask[b*L_ + l] < -10.f;
    g_scores[(b*NH_+0)*L_ + l] = pad ? -INFINITY : a0*inv_sqrt_d;
    g_scores[(b*NH_+1)*L_ + l] = pad ? -INFINITY : a1*inv_sqrt_d;
    g_scores[(b*NH_+2)*L_ + l] = pad ? -INFINITY : a2*inv_sqrt_d;
    g_scores[(b*NH_+3)*L_ + l] = pad ? -INFINITY : a3*inv_sqrt_d;
  }
}

// ---------------------------------------------------------------------------
// Fused softmax + weighted-hidden partials.  grid (B, 16), 768 threads.
__global__ void __launch_bounds__(768) k_wacc(const float* __restrict__ hs){
  __shared__ float s_p[NH_*L_];
  __shared__ float red[32];
  int b = blockIdx.x, ch = blockIdx.y;
  int tid = threadIdx.x, wid = tid>>5, lane = tid&31;
  #pragma unroll
  for (int h = 0; h < NH_; h++){
    float v = (tid < L_) ? g_scores[(b*NH_+h)*L_ + tid] : -INFINITY;
    float m = block_max(v, red, wid, lane, 24);
    float e = (tid < L_) ? expf(v - m) : 0.f;
    float ssum = block_sum(e, red, wid, lane, 24);
    if (tid < L_) s_p[h*L_ + tid] = e / ssum;
  }
  __syncthreads();
  float a0=0.f,a1=0.f,a2=0.f,a3=0.f;
  int l0 = ch*32;
  const float* hb = hs + ((size_t)b*L_ + l0)*D_ + tid;
  #pragma unroll 2
  for (int l = 0; l < 32; l++){
    float hv = hb[(size_t)l*D_];
    a0 += s_p[0*L_ + l0+l]*hv;
    a1 += s_p[1*L_ + l0+l]*hv;
    a2 += s_p[2*L_ + l0+l]*hv;
    a3 += s_p[3*L_ + l0+l]*hv;
  }
  float* wp = g_w_part + (size_t)((b*16 + ch)*NH_)*D_ + tid;
  wp[0*D_] = a0; wp[1*D_] = a1; wp[2*D_] = a2; wp[3*D_] = a3;
}

// ---------------------------------------------------------------------------
// o[b,u] = w[b,h(u)]·Wv[u,:], reducing the 16 w-partials in-block.
// grid (B, 32), 256 threads; warp per u; block ch covers one head (8 | 64).
__global__ void __launch_bounds__(256) k_o(const float* __restrict__ Wv){
  __shared__ __align__(16) float s_w[D_];
  int b = blockIdx.x, ch = blockIdx.y;
  int tid = threadIdx.x, wid = tid>>5, lane = tid&31;
  int h = (ch*8) >> 6;
  if (tid < 192){
    float4 a = make_float4(0.f,0.f,0.f,0.f);
    #pragma unroll
    for (int c = 0; c < 16; c++){
      float4 v = ((const float4*)(g_w_part + (size_t)((b*16 + c)*NH_ + h)*D_))[tid];
      a.x += v.x; a.y += v.y; a.z += v.z; a.w += v.w;
    }
    ((float4*)s_w)[tid] = a;
  }
  __syncthreads();
  const float4* w4 = (const float4*)s_w;
  int u = ch*8 + wid;
  const float4* vr = (const float4*)(Wv + (size_t)u*D_);
  float acc = 0.f;
  #pragma unroll
  for (int k = 0; k < 6; k++) acc += dot4(w4[lane + 32*k], vr[lane + 32*k]);
  acc = warp_sum(acc);
  if (lane==0) g_o[b*U_ + u] = acc;
}

// ---------------------------------------------------------------------------
// new_token[b,d] = o[b,:]·Wo[d,:] + bo[d]   grid (B, 96), 256 threads; warp per d
__global__ void __launch_bounds__(256) k_ntok(const float* __restrict__ Wo,
                                              const float* __restrict__ bo){
  __shared__ __align__(16) float s_o[U_];
  int b = blockIdx.x, ch = blockIdx.y;
  int tid = threadIdx.x, wid = tid>>5, lane = tid&31;
  if (tid < 64) ((float4*)s_o)[tid] = ((const float4*)(g_o + b*U_))[tid];
  __syncthreads();
  int d = ch*8 + wid;
  const float4* wr = (const float4*)(Wo + (size_t)d*U_);
  const float4* o4 = (const float4*)s_o;
  float acc = dot4(o4[lane], wr[lane]) + dot4(o4[lane+32], wr[lane+32]);
  acc = warp_sum(acc);
  if (lane==0) g_newtok[b*D_ + d] = acc + bo[d];
}

// ---------------------------------------------------------------------------
// Assemble: final_token (B,130,768) then final_attention_mask (B,130).
// grid B*130, 192 threads (float4 rows).
__global__ void __launch_bounds__(192) k_assemble(const float* __restrict__ hs,
                                                  const float* __restrict__ mask,
                                                  float* __restrict__ out){
  int r = blockIdx.x % 130;
  int b = blockIdx.x / 130;
  int tid = threadIdx.x;
  const float* src;
  float mval = 0.f;
  if (r == 0){
    src = hs + (size_t)b*L_*D_;
  } else if (r < 129){
    int idx = g_idx[b*K_ + r - 1];
    src = hs + ((size_t)b*L_ + idx)*D_;
    mval = mask[b*L_ + idx];
  } else {
    src = g_newtok + b*D_;
  }
  float4 val = ((const float4*)src)[tid];
  ((float4*)(out + (size_t)(b*130 + r)*D_))[tid] = val;
  if (tid == 0) out[(size_t)B_*130*D_ + b*130 + r] = mval;
}

// ---------------------------------------------------------------------------
extern "C" void kernel_launch(void* const* d_in, const int* in_sizes, int n_in,
                              void* d_out, int out_size) {
  const float* hs   = (const float*)d_in[0]; // hidden_states (B,L,D)
  const float* mask = (const float*)d_in[1]; // attention_mask (B,1,1,L)
  const float* sas  = (const float*)d_in[2]; // self_attention_scores (B,H,L,L)
  const float* Wq   = (const float*)d_in[3];
  const float* Wk   = (const float*)d_in[4];
  const float* Wv   = (const float*)d_in[5];
  const float* Wo   = (const float*)d_in[6];
  const float* bo   = (const float*)d_in[7];
  float* out = (float*)d_out;

  // Lazy-create side streams + events (first call is NOT captured).
  static cudaStream_t s2 = 0, s3 = 0;
  static cudaEvent_t ev_fork = 0, ev_imp = 0, ev_warm = 0;
  if (!s2){
    cudaStreamCreateWithFlags(&s2, cudaStreamNonBlocking);
    cudaStreamCreateWithFlags(&s3, cudaStreamNonBlocking);
    cudaEventCreateWithFlags(&ev_fork, cudaEventDisableTiming);
    cudaEventCreateWithFlags(&ev_imp, cudaEventDisableTiming);
    cudaEventCreateWithFlags(&ev_warm, cudaEventDisableTiming);
  }

  cudaEventRecord(ev_fork, 0);
  // s2: DRAM-bound importance chain (cache-streaming loads, wide grid)
  cudaStreamWaitEvent(s2, ev_fork, 0);
  k_importance<<<dim3(B_, 48), 256, 0, s2>>>(sas);
  k_topk<<<B_, 512, 0, s2>>>();
  cudaEventRecord(ev_imp, s2);
  // s3: warm the weights into L2 (joined back before assemble)
  cudaStreamWaitEvent(s3, ev_fork, 0);
  k_warm<<<768, 256, 0, s3>>>((const float4*)Wq, (const float4*)Wk,
                              (const float4*)Wv, (const float4*)Wo);
  cudaEventRecord(ev_warm, s3);

  // main attention chain (latency-bound, all wide grids)
  k_sent<<<dim3(B_, 16), 768>>>(hs, mask);
  k_q<<<dim3(B_, 32), 256>>>(Wq);
  k_t<<<dim3(B_, NH_, 6), 128>>>(Wk);
  k_scores<<<dim3(B_, 32), 512>>>(hs, mask);
  k_wacc<<<dim3(B_, 16), 768>>>(hs);
  k_o<<<dim3(B_, 32), 256>>>(Wv);
  k_ntok<<<dim3(B_, 96), 256>>>(Wo, bo);

  // join both side streams before the final kernel
  cudaStreamWaitEvent(0, ev_imp, 0);
  cudaStreamWaitEvent(0, ev_warm, 0);
  k_assemble<<<B_*130, 192>>>(hs, mask, out);
}

// round 11
// speedup vs baseline: 1.1045x; 1.1045x over previous
#include <cuda_runtime.h>
#include <math.h>

// Problem constants
#define B_ 16
#define L_ 512
#define D_ 768
#define H_ 12
#define K_ 128
#define U_ 256
#define NH_ 4
#define HD_ 64

// Scratch (no init needed: fully overwritten every replay)
static __device__ __align__(16) float g_imp_part[B_*24*L_];     // (b, chunk24, l)
static __device__ __align__(16) float g_sent_part[B_*16*D_];    // (b, chunk16, d)
static __device__ __align__(16) float g_t[B_*NH_*D_];
static __device__ __align__(16) float g_scores[B_*NH_*L_];
static __device__ __align__(16) float g_w_part[B_*16*NH_*D_];   // (b, chunk16, h, d)
static __device__ __align__(16) float g_w[B_*NH_*D_];
static __device__ __align__(16) float g_o[B_*U_];
static __device__ __align__(16) float g_newtok[B_*D_];
static __device__ float g_warm[1024];
static __device__ int   g_idx[B_*K_];

__device__ __forceinline__ float warp_max(float v){
  #pragma unroll
  for (int o=16;o;o>>=1) v = fmaxf(v, __shfl_xor_sync(0xffffffffu, v, o));
  return v;
}
__device__ __forceinline__ float warp_sum(float v){
  #pragma unroll
  for (int o=16;o;o>>=1) v += __shfl_xor_sync(0xffffffffu, v, o);
  return v;
}
__device__ __forceinline__ float block_max(float v, float* red, int wid, int lane, int nw){
  v = warp_max(v);
  if (lane==0) red[wid] = v;
  __syncthreads();
  if (wid==0){
    float x = (lane < nw) ? red[lane] : -INFINITY;
    x = warp_max(x);
    if (lane==0) red[0] = x;
  }
  __syncthreads();
  float r = red[0];
  __syncthreads();
  return r;
}
__device__ __forceinline__ float block_sum(float v, float* red, int wid, int lane, int nw){
  v = warp_sum(v);
  if (lane==0) red[wid] = v;
  __syncthreads();
  if (wid==0){
    float x = (lane < nw) ? red[lane] : 0.f;
    x = warp_sum(x);
    if (lane==0) red[0] = x;
  }
  __syncthreads();
  float r = red[0];
  __syncthreads();
  return r;
}
__device__ __forceinline__ float dot4(float4 a, float4 b){
  return a.x*b.x + a.y*b.y + a.z*b.z + a.w*b.w;
}

// ---------------------------------------------------------------------------
// Warm L2 with the weight matrices (deterministic, result unused downstream).
// grid 768, 256 threads: 4 matrices x 49152 float4 = 3 MB.
__global__ void __launch_bounds__(256) k_warm(const float4* __restrict__ Wq,
                                              const float4* __restrict__ Wk,
                                              const float4* __restrict__ Wv,
                                              const float4* __restrict__ Wo){
  int i = blockIdx.x*256 + threadIdx.x;   // 0 .. 196607
  int m = i / 49152;
  const float4* src = (m==0) ? Wq : (m==1) ? Wk : (m==2) ? Wv : Wo;
  int off = i - m*49152;
  float4 v = src[off];
  float s = v.x + v.y + v.z + v.w;
  s = warp_sum(s);
  if (threadIdx.x == 0)
    g_warm[blockIdx.x] = s;
}

// ---------------------------------------------------------------------------
// importance partials: g_imp_part[b,ch,l] = (1/H)*sum_{256 rows} sas[b,rows,l]
// grid (B, 24), 256 threads. __ldcs: the 201 MB is read exactly once —
// evict-first so hidden_states stays L2-resident for the attention chain.
__global__ void __launch_bounds__(256) k_importance(const float* __restrict__ s){
  __shared__ float4 s_half[128];
  int b = blockIdx.x, ch = blockIdx.y;
  int col = threadIdx.x & 127;
  int rh  = threadIdx.x >> 7;
  const float4* base = (const float4*)s + (size_t)(b*H_*L_ + ch*256) * (L_/4);
  float4 acc = make_float4(0.f,0.f,0.f,0.f);
  #pragma unroll 8
  for (int r = rh; r < 256; r += 2){
    float4 v = __ldcs(&base[(size_t)r*(L_/4) + col]);
    acc.x += v.x; acc.y += v.y; acc.z += v.z; acc.w += v.w;
  }
  if (rh == 1) s_half[col] = acc;
  __syncthreads();
  if (rh == 0){
    const float sc = 1.0f/(float)H_;
    float4 o = s_half[col];
    o.x = (o.x + acc.x)*sc; o.y = (o.y + acc.y)*sc;
    o.z = (o.z + acc.z)*sc; o.w = (o.w + acc.w)*sc;
    __stcs(&((float4*)(g_imp_part + (size_t)(b*24 + ch)*L_))[col], o);
  }
}

// ---------------------------------------------------------------------------
// top-K: reduce 24 partials, rank with jax tie rule, compact by index.
__global__ void __launch_bounds__(512) k_topk(){
  __shared__ float v[L_];
  __shared__ int flag[L_];
  int b = blockIdx.x, tid = threadIdx.x;
  float acc = 0.f;
  #pragma unroll
  for (int c = 0; c < 24; c++)
    acc += g_imp_part[(size_t)(b*24 + c)*L_ + tid];
  v[tid] = acc;
  __syncthreads();
  float mv = v[tid];
  int r = 0;
  #pragma unroll 8
  for (int j = 0; j < L_; j++){
    float o = v[j];
    r += (o > mv) || (o == mv && j < tid);
  }
  int sel = (r < K_) ? 1 : 0;
  flag[tid] = sel;
  __syncthreads();
  if (sel){
    int pos = 0;
    for (int j = 0; j < tid; j++) pos += flag[j];
    g_idx[b*K_ + pos] = tid;
  }
}

// ---------------------------------------------------------------------------
// Fused mask-softmax + sentence partials.  grid (B, 16), 768 threads;
// each block handles 32 l's -> g_sent_part[b,ch,:]
__global__ void __launch_bounds__(768) k_sent(const float* __restrict__ hs,
                                              const float* __restrict__ mask){
  __shared__ float s_att[L_];
  __shared__ float red[32];
  int b = blockIdx.x, ch = blockIdx.y;
  int tid = threadIdx.x, wid = tid>>5, lane = tid&31;
  float mv = (tid < L_) ? mask[b*L_ + tid] : -INFINITY;
  float m = block_max(mv, red, wid, lane, 24);
  float e = (tid < L_) ? expf(mv - m) : 0.f;
  float ssum = block_sum(e, red, wid, lane, 24);
  if (tid < L_) s_att[tid] = e / ssum;
  __syncthreads();
  float acc = 0.f;
  int l0 = ch*32;
  const float* hb = hs + ((size_t)b*L_ + l0)*D_ + tid;
  #pragma unroll 8
  for (int l = 0; l < 32; l++)
    acc += s_att[l0+l] * hb[(size_t)l*D_];
  g_sent_part[(size_t)(b*16 + ch)*D_ + tid] = acc;
}

// ---------------------------------------------------------------------------
// Fused q+t: block (b,h,z) reduces sent partials, computes its head's 64
// q-values in-block, then t[b,h, z*128 .. z*128+127].
// grid (B, NH, 6), 128 threads.
__global__ void __launch_bounds__(128) k_qt(const float* __restrict__ Wq,
                                            const float* __restrict__ Wk){
  __shared__ __align__(16) float s_sent[D_];
  __shared__ float s_q[HD_];
  int b = blockIdx.x, h = blockIdx.y, z = blockIdx.z;
  int tid = threadIdx.x, wid = tid>>5, lane = tid&31;
  // phase A: reduce 16 sentence partials (192 float4)
  for (int i = tid; i < 192; i += 128){
    float4 a = make_float4(0.f,0.f,0.f,0.f);
    #pragma unroll
    for (int c = 0; c < 16; c++){
      float4 v = ((const float4*)(g_sent_part + (size_t)(b*16 + c)*D_))[i];
      a.x += v.x; a.y += v.y; a.z += v.z; a.w += v.w;
    }
    ((float4*)s_sent)[i] = a;
  }
  __syncthreads();
  // phase B: 4 warps x 16 j -> q for this head
  const float4* s4 = (const float4*)s_sent;
  #pragma unroll
  for (int jj = 0; jj < 16; jj++){
    int j = wid*16 + jj;
    const float4* wr = (const float4*)(Wq + (size_t)(h*HD_ + j)*D_);
    float acc = 0.f;
    #pragma unroll
    for (int k = 0; k < 6; k++) acc += dot4(s4[lane + 32*k], wr[lane + 32*k]);
    acc = warp_sum(acc);
    if (lane==0) s_q[j] = acc;
  }
  __syncthreads();
  // phase C: one t element per thread (64-deep strided loads, high MLP)
  int d = z*128 + tid;
  const float* wk = Wk + (size_t)h*HD_*D_ + d;
  float acc = 0.f;
  #pragma unroll 16
  for (int j = 0; j < HD_; j++)
    acc += s_q[j] * wk[(size_t)j*D_];
  g_t[(b*NH_+h)*D_ + d] = acc;
}

// ---------------------------------------------------------------------------
// scores[b,h,l] = (t[b,h]·hidden[b,l]) / sqrt(D), masked -> -inf
// grid (B, 32), 512 threads (16 warps); warp per l
__global__ void __launch_bounds__(512) k_scores(const float* __restrict__ hs,
                                                const float* __restrict__ mask){
  __shared__ __align__(16) float s_t[NH_*D_];
  int b = blockIdx.x, ch = blockIdx.y;
  int tid = threadIdx.x, wid = tid>>5, lane = tid&31;
  for (int i = tid; i < NH_*192; i += 512)
    ((float4*)s_t)[i] = ((const float4*)(g_t + b*NH_*D_))[i];
  __syncthreads();
  const float4* t4 = (const float4*)s_t;
  const float inv_sqrt_d = 0.03608439182435161f; // 1/sqrt(768)
  int l = ch*16 + wid;
  const float4* hr = (const float4*)(hs + ((size_t)b*L_ + l)*D_);
  float a0=0.f,a1=0.f,a2=0.f,a3=0.f;
  #pragma unroll
  for (int k = 0; k < 6; k++){
    float4 v  = hr[lane + 32*k];
    a0 += dot4(v, t4[0*192 + lane + 32*k]);
    a1 += dot4(v, t4[1*192 + lane + 32*k]);
    a2 += dot4(v, t4[2*192 + lane + 32*k]);
    a3 += dot4(v, t4[3*192 + lane + 32*k]);
  }
  a0 = warp_sum(a0); a1 = warp_sum(a1); a2 = warp_sum(a2); a3 = warp_sum(a3);
  if (lane == 0){
    bool pad = mask[b*L_ + l] < -10.f;
    g_scores[(b*NH_+0)*L_ + l] = pad ? -INFINITY : a0*inv_sqrt_d;
    g_scores[(b*NH_+1)*L_ + l] = pad ? -INFINITY : a1*inv_sqrt_d;
    g_scores[(b*NH_+2)*L_ + l] = pad ? -INFINITY : a2*inv_sqrt_d;
    g_scores[(b*NH_+3)*L_ + l] = pad ? -INFINITY : a3*inv_sqrt_d;
  }
}

// ---------------------------------------------------------------------------
// Fused softmax + weighted-hidden partials.  grid (B, 16), 768 threads.
__global__ void __launch_bounds__(768) k_wacc(const float* __restrict__ hs){
  __shared__ float s_p[NH_*L_];
  __shared__ float red[32];
  int b = blockIdx.x, ch = blockIdx.y;
  int tid = threadIdx.x, wid = tid>>5, lane = tid&31;
  #pragma unroll
  for (int h = 0; h < NH_; h++){
    float v = (tid < L_) ? g_scores[(b*NH_+h)*L_ + tid] : -INFINITY;
    float m = block_max(v, red, wid, lane, 24);
    float e = (tid < L_) ? expf(v - m) : 0.f;
    float ssum = block_sum(e, red, wid, lane, 24);
    if (tid < L_) s_p[h*L_ + tid] = e / ssum;
  }
  __syncthreads();
  float a0=0.f,a1=0.f,a2=0.f,a3=0.f;
  int l0 = ch*32;
  const float* hb = hs + ((size_t)b*L_ + l0)*D_ + tid;
  #pragma unroll 2
  for (int l = 0; l < 32; l++){
    float hv = hb[(size_t)l*D_];
    a0 += s_p[0*L_ + l0+l]*hv;
    a1 += s_p[1*L_ + l0+l]*hv;
    a2 += s_p[2*L_ + l0+l]*hv;
    a3 += s_p[3*L_ + l0+l]*hv;
  }
  float* wp = g_w_part + (size_t)((b*16 + ch)*NH_)*D_ + tid;
  wp[0*D_] = a0; wp[1*D_] = a1; wp[2*D_] = a2; wp[3*D_] = a3;
}

// ---------------------------------------------------------------------------
// w[b] = sum of 16 partials.  grid B, 768 threads (float4 per thread, 16 deep)
__global__ void __launch_bounds__(768) k_wred(){
  int b = blockIdx.x, tid = threadIdx.x;
  float4 a = make_float4(0.f,0.f,0.f,0.f);
  #pragma unroll
  for (int c = 0; c < 16; c++){
    float4 v = ((const float4*)(g_w_part + (size_t)((b*16 + c)*NH_)*D_))[tid];
    a.x += v.x; a.y += v.y; a.z += v.z; a.w += v.w;
  }
  ((float4*)(g_w + (size_t)b*NH_*D_))[tid] = a;
}

// ---------------------------------------------------------------------------
// o[b,u] = w[b,h(u)]·Wv[u,:]   grid (B, 32), 256 threads; warp per u
// Block ch covers u in [ch*8, ch*8+8) -> single head (8 | 64).
__global__ void __launch_bounds__(256) k_o(const float* __restrict__ Wv){
  __shared__ __align__(16) float s_w[D_];
  int b = blockIdx.x, ch = blockIdx.y;
  int tid = threadIdx.x, wid = tid>>5, lane = tid&31;
  int h = (ch*8) >> 6;
  if (tid < 192)
    ((float4*)s_w)[tid] = ((const float4*)(g_w + ((size_t)b*NH_ + h)*D_))[tid];
  __syncthreads();
  const float4* w4 = (const float4*)s_w;
  int u = ch*8 + wid;
  const float4* vr = (const float4*)(Wv + (size_t)u*D_);
  float acc = 0.f;
  #pragma unroll
  for (int k = 0; k < 6; k++) acc += dot4(w4[lane + 32*k], vr[lane + 32*k]);
  acc = warp_sum(acc);
  if (lane==0) g_o[b*U_ + u] = acc;
}

// ---------------------------------------------------------------------------
// new_token[b,d] = o[b,:]·Wo[d,:] + bo[d]   grid (B, 96), 256 threads; warp per d
__global__ void __launch_bounds__(256) k_ntok(const float* __restrict__ Wo,
                                              const float* __restrict__ bo){
  __shared__ __align__(16) float s_o[U_];
  int b = blockIdx.x, ch = blockIdx.y;
  int tid = threadIdx.x, wid = tid>>5, lane = tid&31;
  if (tid < 64) ((float4*)s_o)[tid] = ((const float4*)(g_o + b*U_))[tid];
  __syncthreads();
  int d = ch*8 + wid;
  const float4* wr = (const float4*)(Wo + (size_t)d*U_);
  const float4* o4 = (const float4*)s_o;
  float acc = dot4(o4[lane], wr[lane]) + dot4(o4[lane+32], wr[lane+32]);
  acc = warp_sum(acc);
  if (lane==0) g_newtok[b*D_ + d] = acc + bo[d];
}

// ---------------------------------------------------------------------------
// Assemble: final_token (B,130,768) then final_attention_mask (B,130).
// grid B*130, 192 threads (float4 rows).
__global__ void __launch_bounds__(192) k_assemble(const float* __restrict__ hs,
                                                  const float* __restrict__ mask,
                                                  float* __restrict__ out){
  int r = blockIdx.x % 130;
  int b = blockIdx.x / 130;
  int tid = threadIdx.x;
  const float* src;
  float mval = 0.f;
  if (r == 0){
    src = hs + (size_t)b*L_*D_;
  } else if (r < 129){
    int idx = g_idx[b*K_ + r - 1];
    src = hs + ((size_t)b*L_ + idx)*D_;
    mval = mask[b*L_ + idx];
  } else {
    src = g_newtok + b*D_;
  }
  float4 val = ((const float4*)src)[tid];
  ((float4*)(out + (size_t)(b*130 + r)*D_))[tid] = val;
  if (tid == 0) out[(size_t)B_*130*D_ + b*130 + r] = mval;
}

// ---------------------------------------------------------------------------
extern "C" void kernel_launch(void* const* d_in, const int* in_sizes, int n_in,
                              void* d_out, int out_size) {
  const float* hs   = (const float*)d_in[0]; // hidden_states (B,L,D)
  const float* mask = (const float*)d_in[1]; // attention_mask (B,1,1,L)
  const float* sas  = (const float*)d_in[2]; // self_attention_scores (B,H,L,L)
  const float* Wq   = (const float*)d_in[3];
  const float* Wk   = (const float*)d_in[4];
  const float* Wv   = (const float*)d_in[5];
  const float* Wo   = (const float*)d_in[6];
  const float* bo   = (const float*)d_in[7];
  float* out = (float*)d_out;

  // Lazy-create side streams + events (first call is NOT captured).
  static cudaStream_t s2 = 0, s3 = 0;
  static cudaEvent_t ev_fork = 0, ev_imp = 0, ev_warm = 0;
  if (!s2){
    cudaStreamCreateWithFlags(&s2, cudaStreamNonBlocking);
    cudaStreamCreateWithFlags(&s3, cudaStreamNonBlocking);
    cudaEventCreateWithFlags(&ev_fork, cudaEventDisableTiming);
    cudaEventCreateWithFlags(&ev_imp, cudaEventDisableTiming);
    cudaEventCreateWithFlags(&ev_warm, cudaEventDisableTiming);
  }

  cudaEventRecord(ev_fork, 0);
  // s2: DRAM-bound importance chain (cache-streaming loads)
  cudaStreamWaitEvent(s2, ev_fork, 0);
  k_importance<<<dim3(B_, 24), 256, 0, s2>>>(sas);
  k_topk<<<B_, 512, 0, s2>>>();
  cudaEventRecord(ev_imp, s2);
  // s3: warm the weights into L2 (joined back before assemble)
  cudaStreamWaitEvent(s3, ev_fork, 0);
  k_warm<<<768, 256, 0, s3>>>((const float4*)Wq, (const float4*)Wk,
                              (const float4*)Wv, (const float4*)Wo);
  cudaEventRecord(ev_warm, s3);

  // main attention chain (latency-bound, all wide grids)
  k_sent<<<dim3(B_, 16), 768>>>(hs, mask);
  k_qt<<<dim3(B_, NH_, 6), 128>>>(Wq, Wk);
  k_scores<<<dim3(B_, 32), 512>>>(hs, mask);
  k_wacc<<<dim3(B_, 16), 768>>>(hs);
  k_wred<<<B_, 768>>>();
  k_o<<<dim3(B_, 32), 256>>>(Wv);
  k_ntok<<<dim3(B_, 96), 256>>>(Wo, bo);

  // join both side streams before the final kernel
  cudaStreamWaitEvent(0, ev_imp, 0);
  cudaStreamWaitEvent(0, ev_warm, 0);
  k_assemble<<<B_*130, 192>>>(hs, mask, out);
}